// round 3
// baseline (speedup 1.0000x reference)
#include <cuda_runtime.h>

// LogicGatedSNN: out[o] = (mem[o] + sum_i spike[i]*(states[o,i] > 50) + noise[o] >= thr[o]) ? 1 : 0
// states: [8192, 8192] fp32  -> 256 MB stream, HBM-bound.

#define IN_F 8192
#define OUT_F 8192
#define THREADS 256
#define VEC (IN_F / 4)          // 2048 float4 per row
#define PER_THREAD (VEC / THREADS) // 8 float4 per thread

__global__ __launch_bounds__(THREADS, 4)
void snn_kernel(const float* __restrict__ spike,
                const float* __restrict__ states,
                const float* __restrict__ mem,
                const float* __restrict__ thr,
                const float* __restrict__ noise,
                float* __restrict__ out) {
    __shared__ float4 sx[VEC];           // 32 KB spike vector
    __shared__ float warp_sums[THREADS / 32];

    const int tid = threadIdx.x;
    const int row = blockIdx.x;

    // Stage spike vector into shared (coalesced float4)
    const float4* xg = reinterpret_cast<const float4*>(spike);
#pragma unroll
    for (int i = 0; i < PER_THREAD; i++) {
        sx[tid + i * THREADS] = xg[tid + i * THREADS];
    }
    __syncthreads();

    const float4* s = reinterpret_cast<const float4*>(states) + (size_t)row * VEC;

    float acc = 0.0f;
#pragma unroll
    for (int i = 0; i < PER_THREAD; i++) {
        const int idx = tid + i * THREADS;
        float4 v = __ldg(&s[idx]);
        float4 x = sx[idx];
        acc += (v.x > 50.0f) ? x.x : 0.0f;
        acc += (v.y > 50.0f) ? x.y : 0.0f;
        acc += (v.z > 50.0f) ? x.z : 0.0f;
        acc += (v.w > 50.0f) ? x.w : 0.0f;
    }

    // Warp reduction
#pragma unroll
    for (int off = 16; off > 0; off >>= 1)
        acc += __shfl_xor_sync(0xFFFFFFFFu, acc, off);

    const int warp = tid >> 5;
    const int lane = tid & 31;
    if (lane == 0) warp_sums[warp] = acc;
    __syncthreads();

    if (warp == 0) {
        float v = (lane < THREADS / 32) ? warp_sums[lane] : 0.0f;
#pragma unroll
        for (int off = 4; off > 0; off >>= 1)
            v += __shfl_xor_sync(0xFFFFFFFFu, v, off);
        if (lane == 0) {
            float potential = mem[row] + v + noise[row];
            out[row] = (potential >= thr[row]) ? 1.0f : 0.0f;
        }
    }
}

extern "C" void kernel_launch(void* const* d_in, const int* in_sizes, int n_in,
                              void* d_out, int out_size) {
    const float* spike  = (const float*)d_in[0];
    const float* states = (const float*)d_in[1];
    const float* mem    = (const float*)d_in[2];
    const float* thr    = (const float*)d_in[3];
    const float* noise  = (const float*)d_in[4];
    float* out = (float*)d_out;

    snn_kernel<<<OUT_F, THREADS>>>(spike, states, mem, thr, noise, out);
}